// round 12
// baseline (speedup 1.0000x reference)
#include <cuda_runtime.h>
#include <cstdint>
#include <cstddef>

// ---------------------------------------------------------------------------
// BlocDiagLinear: out[b, n*128+r] = sum_c x[b, n*128+c] * blocks[n, r, c]
// 64 GEMMs (M=4096, N=128, K=128) fp32 -> mma.sync.m16n8k8.tf32, fp32 accum.
//
// R12 = R10 (best: 55.8us) with ONE change: 4 warps @ 64x64 warp tiles
// (was 8 warps @ 32x64). Fragment smem traffic scales with warps*(Mw+Nw):
// 4*128 vs 8*96 -> 33% fewer LDSM bytes, attacking the L1 binder (67.8%).
//   grid (64, 32), CTA tile 128x128x128, 128 threads, 2 CTAs/SM.
//   K in 4 chunks of 32; cp.async 3-stage ring (A 16KB + B 16KB per stage).
//   XOR-swizzled smem (16B atom: c ^= row&7 within 128B rows), ldmatrix.x4.
//   Raw fp32 into tf32 mma (HW truncation) -> rel_err ~7.7e-4, no cvt cost.
// ---------------------------------------------------------------------------

static constexpr int THREADS = 128;
static constexpr int STAGE_BYTES = 32768;            // A 16KB + B 16KB
static constexpr int SMEM_BYTES  = 3 * STAGE_BYTES;  // 98304 -> 2 CTAs/SM

__device__ __forceinline__ uint32_t smem_u32(const void* p) {
    uint32_t a;
    asm("{ .reg .u64 t; cvta.to.shared.u64 t, %1; cvt.u32.u64 %0, t; }"
        : "=r"(a) : "l"(p));
    return a;
}

// Issue one K=32 chunk (A: x tile, B: blocks[n]) via cp.async (128 threads).
__device__ __forceinline__ void issue_stage(uint32_t sbase,
                                            const float* __restrict__ xg,
                                            const float* __restrict__ bg,
                                            int s)
{
    #pragma unroll
    for (int it = 0; it < 8; it++) {
        const int j   = threadIdx.x + it * 128;   // 0..1023 int4 atoms
        const int row = j >> 3;                   // 0..127
        const int c   = j & 7;                    // 16B atom within 128B row
        const uint32_t sw = (uint32_t)((c ^ (row & 7)) << 4);
        const uint32_t dA = sbase + row * 128 + sw;
        const float* sA = xg + (size_t)row * 8192 + s * 32 + c * 4;
        asm volatile("cp.async.cg.shared.global [%0], [%1], 16;"
                     :: "r"(dA), "l"(sA));
        const uint32_t dB = sbase + 16384 + row * 128 + sw;
        const float* sB = bg + row * 128 + s * 32 + c * 4;
        asm volatile("cp.async.cg.shared.global [%0], [%1], 16;"
                     :: "r"(dB), "l"(sB));
    }
    asm volatile("cp.async.commit_group;" ::: "memory");
}

// Compute one K=32 chunk (4 k-steps of m16n8k8), warp tile 64x64.
// Raw fp32 fragments feed the tf32 mma; HW truncates to tf32.
__device__ __forceinline__ void compute_stage(uint32_t abase, uint32_t bbase,
                                              int mrow, int ncol, int lane,
                                              float acc[4][8][4])
{
    const int t4 = lane >> 3;     // tile index within ldmatrix.x4
    const int tr = lane & 7;      // row within tile

    #pragma unroll
    for (int kk = 0; kk < 4; kk++) {
        // ---- A fragments: 4 x ldmatrix.x4 (rows mrow+16i, k cols 8*kk..+8)
        uint32_t a[4][4];
        #pragma unroll
        for (int i = 0; i < 4; i++) {
            const int r = mrow + 16 * i + ((t4 & 1) << 3) + tr;
            const int c = 2 * kk + (t4 >> 1);
            const uint32_t addr = abase + r * 128 + ((uint32_t)(c ^ (r & 7)) << 4);
            asm volatile(
                "ldmatrix.sync.aligned.m8n8.x4.shared.b16 {%0,%1,%2,%3}, [%4];"
                : "=r"(a[i][0]), "=r"(a[i][1]), "=r"(a[i][2]), "=r"(a[i][3])
                : "r"(addr));
        }

        // ---- B fragments: 4 x ldmatrix.x4 cover jj pairs {0,1},{2,3},{4,5},{6,7}
        uint32_t b[8][2];
        #pragma unroll
        for (int p = 0; p < 4; p++) {
            const int rn = ncol + (2 * p + (t4 >> 1)) * 8 + tr;
            const int c  = 2 * kk + (t4 & 1);
            const uint32_t addr = bbase + rn * 128 + ((uint32_t)(c ^ (rn & 7)) << 4);
            asm volatile(
                "ldmatrix.sync.aligned.m8n8.x4.shared.b16 {%0,%1,%2,%3}, [%4];"
                : "=r"(b[2 * p][0]), "=r"(b[2 * p][1]),
                  "=r"(b[2 * p + 1][0]), "=r"(b[2 * p + 1][1])
                : "r"(addr));
        }

        // ---- 32 mma per k-step (4 M-groups x 8 N-groups)
        #pragma unroll
        for (int jj = 0; jj < 8; jj++)
            #pragma unroll
            for (int i = 0; i < 4; i++) {
                asm volatile(
                    "mma.sync.aligned.m16n8k8.row.col.f32.tf32.tf32.f32 "
                    "{%0,%1,%2,%3}, {%4,%5,%6,%7}, {%8,%9}, {%0,%1,%2,%3};"
                    : "+f"(acc[i][jj][0]), "+f"(acc[i][jj][1]),
                      "+f"(acc[i][jj][2]), "+f"(acc[i][jj][3])
                    : "r"(a[i][0]), "r"(a[i][1]), "r"(a[i][2]), "r"(a[i][3]),
                      "r"(b[jj][0]), "r"(b[jj][1]));
            }
    }
}

__global__ void __launch_bounds__(THREADS, 2)
bdl_mma_kernel(const float* __restrict__ x,
               const float* __restrict__ blocks,
               float* __restrict__ out)
{
    extern __shared__ char smem[];
    const uint32_t sb = smem_u32(smem);

    const int tid  = threadIdx.x;
    const int wid  = tid >> 5;           // 0..3
    const int lane = tid & 31;
    const int g    = lane >> 2;
    const int tig  = lane & 3;

    const int n  = blockIdx.x;
    const int m0 = blockIdx.y * 128;

    const int mrow = (wid >> 1) * 64;    // 2 warps along M
    const int ncol = (wid & 1) * 64;     // 2 warps along N

    const float* xg = x + (size_t)m0 * 8192 + n * 128;
    const float* bg = blocks + (size_t)n * 16384;

    float acc[4][8][4];
    #pragma unroll
    for (int i = 0; i < 4; i++)
        #pragma unroll
        for (int j = 0; j < 8; j++)
            #pragma unroll
            for (int v = 0; v < 4; v++)
                acc[i][j][v] = 0.0f;

    // ---- prologue: fill ring with stages 0..2 ----
    issue_stage(sb + 0 * STAGE_BYTES, xg, bg, 0);
    issue_stage(sb + 1 * STAGE_BYTES, xg, bg, 1);
    issue_stage(sb + 2 * STAGE_BYTES, xg, bg, 2);

    // ---- stage 0 ----
    asm volatile("cp.async.wait_group 2;" ::: "memory");
    __syncthreads();
    compute_stage(sb + 0 * STAGE_BYTES, sb + 0 * STAGE_BYTES + 16384,
                  mrow, ncol, lane, acc);
    __syncthreads();                       // buf0 free before reuse
    issue_stage(sb + 0 * STAGE_BYTES, xg, bg, 3);

    // ---- stage 1 ----
    asm volatile("cp.async.wait_group 2;" ::: "memory");
    __syncthreads();
    compute_stage(sb + 1 * STAGE_BYTES, sb + 1 * STAGE_BYTES + 16384,
                  mrow, ncol, lane, acc);

    // ---- stage 2 ----
    asm volatile("cp.async.wait_group 1;" ::: "memory");
    __syncthreads();
    compute_stage(sb + 2 * STAGE_BYTES, sb + 2 * STAGE_BYTES + 16384,
                  mrow, ncol, lane, acc);

    // ---- stage 3 (in buf0) ----
    asm volatile("cp.async.wait_group 0;" ::: "memory");
    __syncthreads();
    compute_stage(sb + 0 * STAGE_BYTES, sb + 0 * STAGE_BYTES + 16384,
                  mrow, ncol, lane, acc);

    // ---- epilogue: float2 stores (each quad fills a full 32B sector) ----
    float* obase = out + (size_t)m0 * 8192 + n * 128;
    #pragma unroll
    for (int i = 0; i < 4; i++) {
        const int r0 = mrow + 16 * i + g;
        #pragma unroll
        for (int jj = 0; jj < 8; jj++) {
            const int c = ncol + 8 * jj + 2 * tig;
            *reinterpret_cast<float2*>(obase + (size_t)r0 * 8192 + c) =
                make_float2(acc[i][jj][0], acc[i][jj][1]);
            *reinterpret_cast<float2*>(obase + (size_t)(r0 + 8) * 8192 + c) =
                make_float2(acc[i][jj][2], acc[i][jj][3]);
        }
    }
}

extern "C" void kernel_launch(void* const* d_in, const int* in_sizes, int n_in,
                              void* d_out, int out_size)
{
    (void)in_sizes; (void)n_in; (void)out_size;
    const float* x      = (const float*)d_in[0];   // [4096, 8192]
    const float* blocks = (const float*)d_in[1];   // [64, 128, 128]
    float* out          = (float*)d_out;           // [4096, 8192]

    cudaFuncSetAttribute(bdl_mma_kernel,
                         cudaFuncAttributeMaxDynamicSharedMemorySize, SMEM_BYTES);
    dim3 grid(64, 32, 1);
    bdl_mma_kernel<<<grid, THREADS, SMEM_BYTES>>>(x, blocks, out);
}

// round 14
// speedup vs baseline: 1.2216x; 1.2216x over previous
#include <cuda_runtime.h>
#include <cstdint>
#include <cstddef>

// ---------------------------------------------------------------------------
// BlocDiagLinear: out[b, n*128+r] = sum_c x[b, n*128+c] * blocks[n, r, c]
// 64 GEMMs (M=4096, N=128, K=128) fp32 -> mma.sync.m16n8k8.tf32, fp32 accum.
//
// R14 = R13 resubmitted verbatim (R13 bench was an infra failure: the GB300
// container never came up; no kernel evidence was produced).
//
// Persistent CTAs with STATIC pipeline structure (fixing R11's mistakes).
//   grid 296 (2/SM, one wave); CTA walks tiles t = bid + i*296.
//   Per tile: 4 K-chunks of 32 through a 3-buffer ring whose bases live in
//   REGISTERS and rotate once per tile (no modulo, no per-chunk decode).
//   Next tile's chunks 0,1 issue during this tile's chunks 1,2 computes ->
//   epilogue stores overlap in-flight loads; ring fill paid once per CTA.
//   Tail keeps wait_group discipline via empty commit_group.
//   Fragment/mma math identical to R10 (raw fp32 -> HW tf32 truncation).
// ---------------------------------------------------------------------------

static constexpr int THREADS = 256;
static constexpr int NCTA    = 296;
static constexpr int NTILES  = 2048;                 // 64 n-blocks x 32 m-tiles
static constexpr int STAGE_BYTES = 32768;            // A 16KB + B 16KB
static constexpr int SMEM_BYTES  = 3 * STAGE_BYTES;  // 98304 -> 2 CTAs/SM

__device__ __forceinline__ uint32_t smem_u32(const void* p) {
    uint32_t a;
    asm("{ .reg .u64 t; cvta.to.shared.u64 t, %1; cvt.u32.u64 %0, t; }"
        : "=r"(a) : "l"(p));
    return a;
}

// Issue one K=32 chunk (A: x tile, B: blocks[n]) via cp.async.
__device__ __forceinline__ void issue_stage(uint32_t sbase,
                                            const float* __restrict__ xg,
                                            const float* __restrict__ bg,
                                            int s)
{
    #pragma unroll
    for (int it = 0; it < 4; it++) {
        const int j   = threadIdx.x + it * 256;   // 0..1023 int4 atoms
        const int row = j >> 3;                   // 0..127
        const int c   = j & 7;                    // 16B atom within 128B row
        const uint32_t sw = (uint32_t)((c ^ (row & 7)) << 4);
        const uint32_t dA = sbase + row * 128 + sw;
        const float* sA = xg + (size_t)row * 8192 + s * 32 + c * 4;
        asm volatile("cp.async.cg.shared.global [%0], [%1], 16;"
                     :: "r"(dA), "l"(sA));
        const uint32_t dB = sbase + 16384 + row * 128 + sw;
        const float* sB = bg + row * 128 + s * 32 + c * 4;
        asm volatile("cp.async.cg.shared.global [%0], [%1], 16;"
                     :: "r"(dB), "l"(sB));
    }
    asm volatile("cp.async.commit_group;" ::: "memory");
}

#define EMPTY_COMMIT() asm volatile("cp.async.commit_group;" ::: "memory")
#define WAIT2()        asm volatile("cp.async.wait_group 2;" ::: "memory")

// Compute one K=32 chunk (4 k-steps of m16n8k8). Raw fp32 fragments feed the
// tf32 mma directly; HW truncation handles the tf32 conversion.
__device__ __forceinline__ void compute_stage(uint32_t abase, uint32_t bbase,
                                              int mrow, int ncol, int lane,
                                              float acc[2][8][4])
{
    const int t4 = lane >> 3;     // tile index within ldmatrix.x4
    const int tr = lane & 7;      // row within tile

    #pragma unroll
    for (int kk = 0; kk < 4; kk++) {
        uint32_t a[2][4];
        #pragma unroll
        for (int i = 0; i < 2; i++) {
            const int r = mrow + 16 * i + ((t4 & 1) << 3) + tr;
            const int c = 2 * kk + (t4 >> 1);
            const uint32_t addr = abase + r * 128 + ((uint32_t)(c ^ (r & 7)) << 4);
            asm volatile(
                "ldmatrix.sync.aligned.m8n8.x4.shared.b16 {%0,%1,%2,%3}, [%4];"
                : "=r"(a[i][0]), "=r"(a[i][1]), "=r"(a[i][2]), "=r"(a[i][3])
                : "r"(addr));
        }

        uint32_t b[8][2];
        #pragma unroll
        for (int p = 0; p < 4; p++) {
            const int rn = ncol + (2 * p + (t4 >> 1)) * 8 + tr;
            const int c  = 2 * kk + (t4 & 1);
            const uint32_t addr = bbase + rn * 128 + ((uint32_t)(c ^ (rn & 7)) << 4);
            asm volatile(
                "ldmatrix.sync.aligned.m8n8.x4.shared.b16 {%0,%1,%2,%3}, [%4];"
                : "=r"(b[2 * p][0]), "=r"(b[2 * p][1]),
                  "=r"(b[2 * p + 1][0]), "=r"(b[2 * p + 1][1])
                : "r"(addr));
        }

        #pragma unroll
        for (int jj = 0; jj < 8; jj++)
            #pragma unroll
            for (int i = 0; i < 2; i++) {
                asm volatile(
                    "mma.sync.aligned.m16n8k8.row.col.f32.tf32.tf32.f32 "
                    "{%0,%1,%2,%3}, {%4,%5,%6,%7}, {%8,%9}, {%0,%1,%2,%3};"
                    : "+f"(acc[i][jj][0]), "+f"(acc[i][jj][1]),
                      "+f"(acc[i][jj][2]), "+f"(acc[i][jj][3])
                    : "r"(a[i][0]), "r"(a[i][1]), "r"(a[i][2]), "r"(a[i][3]),
                      "r"(b[jj][0]), "r"(b[jj][1]));
            }
    }
}

__global__ void __launch_bounds__(THREADS, 2)
bdl_mma_kernel(const float* __restrict__ x,
               const float* __restrict__ blocks,
               float* __restrict__ out)
{
    extern __shared__ char smem[];
    const uint32_t sb = smem_u32(smem);

    const int tid  = threadIdx.x;
    const int wid  = tid >> 5;
    const int lane = tid & 31;
    const int g    = lane >> 2;
    const int tig  = lane & 3;
    const int bid  = blockIdx.x;

    const int mrow = (wid >> 1) * 32;
    const int ncol = (wid & 1) * 64;

    const int cnt = (NTILES - bid + NCTA - 1) / NCTA;   // 6 or 7 tiles

    // ring buffer bases in registers; rotate once per tile
    uint32_t b0 = sb;
    uint32_t b1 = sb + STAGE_BYTES;
    uint32_t b2 = sb + 2 * STAGE_BYTES;

    float acc[2][8][4];
    #pragma unroll
    for (int i = 0; i < 2; i++)
        #pragma unroll
        for (int j = 0; j < 8; j++)
            #pragma unroll
            for (int v = 0; v < 4; v++)
                acc[i][j][v] = 0.0f;

    // tile 0 pointers
    int t = bid;
    const float* xg = x + (size_t)(t & 31) * (128 * 8192) + (t >> 5) * 128;
    const float* bg = blocks + (size_t)(t >> 5) * 16384;

    // ---- prologue: chunks 0,1 of tile 0 ----
    issue_stage(b0, xg, bg, 0);
    issue_stage(b1, xg, bg, 1);

    for (int i = 0; i < cnt; i++) {
        const bool has_next = (i + 1 < cnt);
        const int  tn = t + NCTA;
        const float* xgn = x + (size_t)(tn & 31) * (128 * 8192) + (tn >> 5) * 128;
        const float* bgn = blocks + (size_t)(tn >> 5) * 16384;

        // chunk 2 of current tile into b2 (b2 last touched >1 barrier ago)
        issue_stage(b2, xg, bg, 2);

        // ---- chunk 0 (b0) ----
        WAIT2(); __syncthreads();
        compute_stage(b0, b0 + 16384, mrow, ncol, lane, acc);
        __syncthreads();
        issue_stage(b0, xg, bg, 3);                    // chunk 3 -> b0

        // ---- chunk 1 (b1) ----
        WAIT2(); __syncthreads();
        compute_stage(b1, b1 + 16384, mrow, ncol, lane, acc);
        __syncthreads();
        if (has_next) issue_stage(b1, xgn, bgn, 0);    // next tile c0 -> b1
        else          EMPTY_COMMIT();

        // ---- chunk 2 (b2) ----
        WAIT2(); __syncthreads();
        compute_stage(b2, b2 + 16384, mrow, ncol, lane, acc);
        __syncthreads();
        if (has_next) issue_stage(b2, xgn, bgn, 1);    // next tile c1 -> b2
        else          EMPTY_COMMIT();

        // ---- chunk 3 (b0) ----
        WAIT2(); __syncthreads();
        compute_stage(b0, b0 + 16384, mrow, ncol, lane, acc);

        // ---- epilogue for tile t (overlaps next tile's in-flight loads) ----
        {
            float* obase = out + (size_t)(t & 31) * (128 * 8192) + (t >> 5) * 128;
            #pragma unroll
            for (int ii = 0; ii < 2; ii++) {
                const int r0 = mrow + 16 * ii + g;
                #pragma unroll
                for (int jj = 0; jj < 8; jj++) {
                    const int c = ncol + 8 * jj + 2 * tig;
                    *reinterpret_cast<float2*>(obase + (size_t)r0 * 8192 + c) =
                        make_float2(acc[ii][jj][0], acc[ii][jj][1]);
                    *reinterpret_cast<float2*>(obase + (size_t)(r0 + 8) * 8192 + c) =
                        make_float2(acc[ii][jj][2], acc[ii][jj][3]);
                    acc[ii][jj][0] = 0.0f; acc[ii][jj][1] = 0.0f;
                    acc[ii][jj][2] = 0.0f; acc[ii][jj][3] = 0.0f;
                }
            }
        }
        __syncthreads();   // b0 (just computed) must drain before next-iter reuse

        // rotate ring: next tile's c0 is in (old) b1, c1 in (old) b2
        const uint32_t tmp = b0;
        b0 = b1; b1 = b2; b2 = tmp;

        t = tn; xg = xgn; bg = bgn;
    }
}

extern "C" void kernel_launch(void* const* d_in, const int* in_sizes, int n_in,
                              void* d_out, int out_size)
{
    (void)in_sizes; (void)n_in; (void)out_size;
    const float* x      = (const float*)d_in[0];   // [4096, 8192]
    const float* blocks = (const float*)d_in[1];   // [64, 128, 128]
    float* out          = (float*)d_out;           // [4096, 8192]

    cudaFuncSetAttribute(bdl_mma_kernel,
                         cudaFuncAttributeMaxDynamicSharedMemorySize, SMEM_BYTES);
    bdl_mma_kernel<<<NCTA, THREADS, SMEM_BYTES>>>(x, blocks, out);
}

// round 15
// speedup vs baseline: 1.4041x; 1.1494x over previous
#include <cuda_runtime.h>
#include <cstdint>
#include <cstddef>

// ---------------------------------------------------------------------------
// BlocDiagLinear: out[b, n*128+r] = sum_c x[b, n*128+c] * blocks[n, r, c]
// 64 GEMMs (M=4096, N=128, K=128) fp32 -> mma.sync.m16n8k8.tf32, fp32 accum.
//
// R15: R10 pipeline + B-reuse across TWO m-tiles per CTA.
//   grid (64, 16): CTA handles m0 = by*256 and m0+128 for one n-block.
//   smem: A ring 3 x 16KB (slots r0..r2) + B static 4 x 16KB (all of
//   blocks[n]) = 112KB -> 2 CTAs/SM (unchanged occupancy).
//   B is cp.async'd ONCE per CTA (halves B L2 reads + B smem stores);
//   tile-2 chunks are A-only and prefetch 3 deep, so tile-1's epilogue
//   overlaps tile-2's loads. Fragment/mma math identical to R10
//   (raw fp32 -> HW tf32 truncation, rel_err 7.7e-4).
// ---------------------------------------------------------------------------

static constexpr int THREADS = 256;
static constexpr int CHUNK_BYTES = 16384;                 // 128 rows x 128B
static constexpr int SMEM_A      = 0;                     // 3 slots
static constexpr int SMEM_B      = 3 * CHUNK_BYTES;       // 4 chunks (static)
static constexpr int SMEM_BYTES  = 7 * CHUNK_BYTES;       // 114688 -> 2 CTAs/SM

__device__ __forceinline__ uint32_t smem_u32(const void* p) {
    uint32_t a;
    asm("{ .reg .u64 t; cvta.to.shared.u64 t, %1; cvt.u32.u64 %0, t; }"
        : "=r"(a) : "l"(p));
    return a;
}

// cp.async one A K=32 chunk (x tile rows, cols s*32..+32) into slot `dst`.
__device__ __forceinline__ void issue_A(uint32_t dst,
                                        const float* __restrict__ xg, int s)
{
    #pragma unroll
    for (int it = 0; it < 4; it++) {
        const int j   = threadIdx.x + it * 256;   // 0..1023 int4 atoms
        const int row = j >> 3;
        const int c   = j & 7;
        const uint32_t sw = (uint32_t)((c ^ (row & 7)) << 4);
        const float* sA = xg + (size_t)row * 8192 + s * 32 + c * 4;
        asm volatile("cp.async.cg.shared.global [%0], [%1], 16;"
                     :: "r"(dst + row * 128 + sw), "l"(sA));
    }
}

// cp.async one B K=32 chunk (blocks[n] rows, cols s*32..+32) into B region.
__device__ __forceinline__ void issue_B(uint32_t bbase,
                                        const float* __restrict__ bg, int s)
{
    #pragma unroll
    for (int it = 0; it < 4; it++) {
        const int j   = threadIdx.x + it * 256;
        const int row = j >> 3;
        const int c   = j & 7;
        const uint32_t sw = (uint32_t)((c ^ (row & 7)) << 4);
        const float* sB = bg + row * 128 + s * 32 + c * 4;
        asm volatile("cp.async.cg.shared.global [%0], [%1], 16;"
                     :: "r"(bbase + (uint32_t)s * CHUNK_BYTES + row * 128 + sw),
                        "l"(sB));
    }
}

#define COMMIT() asm volatile("cp.async.commit_group;" ::: "memory")
#define WAITG(n) asm volatile("cp.async.wait_group %0;" :: "n"(n) : "memory")

// Compute one K=32 chunk (4 k-steps of m16n8k8). Raw fp32 fragments feed the
// tf32 mma directly; HW truncation handles the tf32 conversion. (== R10)
__device__ __forceinline__ void compute_stage(uint32_t abase, uint32_t bbase,
                                              int mrow, int ncol, int lane,
                                              float acc[2][8][4])
{
    const int t4 = lane >> 3;
    const int tr = lane & 7;

    #pragma unroll
    for (int kk = 0; kk < 4; kk++) {
        uint32_t a[2][4];
        #pragma unroll
        for (int i = 0; i < 2; i++) {
            const int r = mrow + 16 * i + ((t4 & 1) << 3) + tr;
            const int c = 2 * kk + (t4 >> 1);
            const uint32_t addr = abase + r * 128 + ((uint32_t)(c ^ (r & 7)) << 4);
            asm volatile(
                "ldmatrix.sync.aligned.m8n8.x4.shared.b16 {%0,%1,%2,%3}, [%4];"
                : "=r"(a[i][0]), "=r"(a[i][1]), "=r"(a[i][2]), "=r"(a[i][3])
                : "r"(addr));
        }

        uint32_t b[8][2];
        #pragma unroll
        for (int p = 0; p < 4; p++) {
            const int rn = ncol + (2 * p + (t4 >> 1)) * 8 + tr;
            const int c  = 2 * kk + (t4 & 1);
            const uint32_t addr = bbase + rn * 128 + ((uint32_t)(c ^ (rn & 7)) << 4);
            asm volatile(
                "ldmatrix.sync.aligned.m8n8.x4.shared.b16 {%0,%1,%2,%3}, [%4];"
                : "=r"(b[2 * p][0]), "=r"(b[2 * p][1]),
                  "=r"(b[2 * p + 1][0]), "=r"(b[2 * p + 1][1])
                : "r"(addr));
        }

        #pragma unroll
        for (int jj = 0; jj < 8; jj++)
            #pragma unroll
            for (int i = 0; i < 2; i++) {
                asm volatile(
                    "mma.sync.aligned.m16n8k8.row.col.f32.tf32.tf32.f32 "
                    "{%0,%1,%2,%3}, {%4,%5,%6,%7}, {%8,%9}, {%0,%1,%2,%3};"
                    : "+f"(acc[i][jj][0]), "+f"(acc[i][jj][1]),
                      "+f"(acc[i][jj][2]), "+f"(acc[i][jj][3])
                    : "r"(a[i][0]), "r"(a[i][1]), "r"(a[i][2]), "r"(a[i][3]),
                      "r"(b[jj][0]), "r"(b[jj][1]));
            }
    }
}

// Store one tile's accumulators (float2 stores) and zero them.
__device__ __forceinline__ void epilogue(float* __restrict__ obase,
                                         int mrow, int ncol, int g, int tig,
                                         float acc[2][8][4])
{
    #pragma unroll
    for (int i = 0; i < 2; i++) {
        const int r0 = mrow + 16 * i + g;
        #pragma unroll
        for (int jj = 0; jj < 8; jj++) {
            const int c = ncol + 8 * jj + 2 * tig;
            *reinterpret_cast<float2*>(obase + (size_t)r0 * 8192 + c) =
                make_float2(acc[i][jj][0], acc[i][jj][1]);
            *reinterpret_cast<float2*>(obase + (size_t)(r0 + 8) * 8192 + c) =
                make_float2(acc[i][jj][2], acc[i][jj][3]);
            acc[i][jj][0] = 0.0f; acc[i][jj][1] = 0.0f;
            acc[i][jj][2] = 0.0f; acc[i][jj][3] = 0.0f;
        }
    }
}

__global__ void __launch_bounds__(THREADS, 2)
bdl_mma_kernel(const float* __restrict__ x,
               const float* __restrict__ blocks,
               float* __restrict__ out)
{
    extern __shared__ char smem[];
    const uint32_t sb  = smem_u32(smem);
    const uint32_t r0s = sb + SMEM_A + 0 * CHUNK_BYTES;
    const uint32_t r1s = sb + SMEM_A + 1 * CHUNK_BYTES;
    const uint32_t r2s = sb + SMEM_A + 2 * CHUNK_BYTES;
    const uint32_t bB  = sb + SMEM_B;

    const int tid  = threadIdx.x;
    const int wid  = tid >> 5;
    const int lane = tid & 31;
    const int g    = lane >> 2;
    const int tig  = lane & 3;

    const int n  = blockIdx.x;                 // diagonal block 0..63
    const int m0 = blockIdx.y * 256;           // this CTA: m0 and m0+128

    const int mrow = (wid >> 1) * 32;
    const int ncol = (wid & 1) * 64;

    const float* xg1 = x + (size_t)m0 * 8192 + n * 128;
    const float* xg2 = xg1 + (size_t)128 * 8192;
    const float* bg  = blocks + (size_t)n * 16384;

    float acc[2][8][4];
    #pragma unroll
    for (int i = 0; i < 2; i++)
        #pragma unroll
        for (int j = 0; j < 8; j++)
            #pragma unroll
            for (int v = 0; v < 4; v++)
                acc[i][j][v] = 0.0f;

    // ---- prologue: groups g0..g2 = (A0+B0, A1+B1, A2+B2) ----
    issue_A(r0s, xg1, 0); issue_B(bB, bg, 0); COMMIT();
    issue_A(r1s, xg1, 1); issue_B(bB, bg, 1); COMMIT();
    issue_A(r2s, xg1, 2); issue_B(bB, bg, 2); COMMIT();

    // ---- tile 1 chunk 0 ----
    WAITG(2); __syncthreads();
    compute_stage(r0s, bB + 0 * CHUNK_BYTES, mrow, ncol, lane, acc);
    __syncthreads();
    issue_A(r0s, xg1, 3); issue_B(bB, bg, 3); COMMIT();   // g3

    // ---- tile 1 chunk 1 ----
    WAITG(2); __syncthreads();
    compute_stage(r1s, bB + 1 * CHUNK_BYTES, mrow, ncol, lane, acc);
    __syncthreads();
    issue_A(r1s, xg2, 0); COMMIT();                       // g4: tile2 A0

    // ---- tile 1 chunk 2 ----
    WAITG(2); __syncthreads();
    compute_stage(r2s, bB + 2 * CHUNK_BYTES, mrow, ncol, lane, acc);
    __syncthreads();
    issue_A(r2s, xg2, 1); COMMIT();                       // g5: tile2 A1

    // ---- tile 1 chunk 3 + epilogue (overlaps tile2 in-flight loads) ----
    WAITG(2); __syncthreads();
    compute_stage(r0s, bB + 3 * CHUNK_BYTES, mrow, ncol, lane, acc);
    epilogue(out + (size_t)m0 * 8192 + n * 128, mrow, ncol, g, tig, acc);
    __syncthreads();
    issue_A(r0s, xg2, 2); COMMIT();                       // g6: tile2 A2

    // ---- tile 2 chunk 0 ----
    WAITG(2); __syncthreads();
    compute_stage(r1s, bB + 0 * CHUNK_BYTES, mrow, ncol, lane, acc);
    __syncthreads();
    issue_A(r1s, xg2, 3); COMMIT();                       // g7: tile2 A3

    // ---- tile 2 chunk 1 ----
    WAITG(2); __syncthreads();
    compute_stage(r2s, bB + 1 * CHUNK_BYTES, mrow, ncol, lane, acc);
    __syncthreads();

    // ---- tile 2 chunk 2 ----
    WAITG(1); __syncthreads();
    compute_stage(r0s, bB + 2 * CHUNK_BYTES, mrow, ncol, lane, acc);
    __syncthreads();

    // ---- tile 2 chunk 3 + epilogue ----
    WAITG(0); __syncthreads();
    compute_stage(r1s, bB + 3 * CHUNK_BYTES, mrow, ncol, lane, acc);
    epilogue(out + (size_t)(m0 + 128) * 8192 + n * 128, mrow, ncol, g, tig, acc);
}

extern "C" void kernel_launch(void* const* d_in, const int* in_sizes, int n_in,
                              void* d_out, int out_size)
{
    (void)in_sizes; (void)n_in; (void)out_size;
    const float* x      = (const float*)d_in[0];   // [4096, 8192]
    const float* blocks = (const float*)d_in[1];   // [64, 128, 128]
    float* out          = (float*)d_out;           // [4096, 8192]

    cudaFuncSetAttribute(bdl_mma_kernel,
                         cudaFuncAttributeMaxDynamicSharedMemorySize, SMEM_BYTES);
    dim3 grid(64, 16, 1);   // (diagonal block n, 256-row m-supertile)
    bdl_mma_kernel<<<grid, THREADS, SMEM_BYTES>>>(x, blocks, out);
}